// round 9
// baseline (speedup 1.0000x reference)
#include <cuda_runtime.h>
#include <cstdint>

#define DM 256
#define DF 1024
#define NE 4
#define NT 65536

// smem pitches (floats) — all hot-loop LDS conflict-free (proven in R6):
//  A-frag uint2 loads need pitch % 32 == 8  -> XP=264, HP=40
//  B-frag scalar loads need 2*pitch % 32 == 8 -> B1P=36, B2P=260
#define XP   264   // X tile  [128 r][256 k]
#define B1P  36    // B1 tile [256 k][32 n]
#define B2P  260   // B2 tile [32 k][256 n]
#define HP   40    // H tile  [128 r][32 k]

#define SM_B1   (128 * XP)             // 33792
#define SM_B2   (SM_B1 + 256 * B1P)    // 43008
#define SM_H    (SM_B2 + 32 * B2P)     // 51328
#define SM_TOK  (SM_H + 128 * HP)      // 56448
#define SM_FLOATS (SM_TOK + 128)       // 56576
#define SM_BYTES  (SM_FLOATS * 4)      // 226304 bytes

__device__ int   g_cnt[NE];
__device__ int   g_list[NE * NT];
__device__ float g_w1[NE * DM * DF];   // native layout, tf32-rounded
__device__ float g_w2[NE * DF * DM];   // native layout, tf32-rounded

__device__ __forceinline__ unsigned tf32_rna(float f) {
    unsigned u;
    asm("cvt.rna.tf32.f32 %0, %1;" : "=r"(u) : "f"(f));
    return u;
}

__device__ __forceinline__ void cp16(void* s, const void* g) {
    uint32_t sa = (uint32_t)__cvta_generic_to_shared(s);
    asm volatile("cp.async.cg.shared.global [%0], [%1], 16;" :: "r"(sa), "l"(g));
}

#define CP_COMMIT() asm volatile("cp.async.commit_group;")
#define CP_WAIT1()  asm volatile("cp.async.wait_group 1;")

// D += A*B for m16n8k8 tf32 (fp32 accumulate)
#define MMA(d, a, b0, b1)                                                    \
    asm volatile(                                                            \
        "mma.sync.aligned.m16n8k8.row.col.f32.tf32.tf32.f32 "                \
        "{%0,%1,%2,%3},{%4,%5,%6,%7},{%8,%9},{%0,%1,%2,%3};"                 \
        : "+f"((d)[0]), "+f"((d)[1]), "+f"((d)[2]), "+f"((d)[3])             \
        : "r"((a)[0]), "r"((a)[1]), "r"((a)[2]), "r"((a)[3]),                \
          "r"(b0), "r"(b1))

// ---------------- prep kernels ----------------

// launch index 0: zero inactive output rows (warp-per-token) + zero counters
__global__ void zero_inactive_cnt_k(const int* __restrict__ b_seq,
                                    float4* __restrict__ out4) {
    if (blockIdx.x == 0 && threadIdx.x < NE) g_cnt[threadIdx.x] = 0;
    int w = (blockIdx.x * blockDim.x + threadIdx.x) >> 5;
    int lane = threadIdx.x & 31;
    if (b_seq[w] == 0) {
        float4 z = make_float4(0.f, 0.f, 0.f, 0.f);
        out4[(size_t)w * 64 + lane] = z;
        out4[(size_t)w * 64 + 32 + lane] = z;
    }
}

// launch index 1
__global__ void build_lists_k(const int* __restrict__ b_seq) {
    int t = blockIdx.x * blockDim.x + threadIdx.x;
    if (t < NT) {
        int b = b_seq[t];
        if (b > 0) {
            int p = atomicAdd(&g_cnt[b - 1], 1);
            g_list[(b - 1) * NT + p] = t;
        }
    }
}

// launch index 2: tf32-round both weight tensors
__global__ void prep_w_k(const float* __restrict__ W1,
                         const float* __restrict__ W2) {
    int i = blockIdx.x * blockDim.x + threadIdx.x;
    if (i < NE * DM * DF) {
        g_w1[i] = __uint_as_float(tf32_rna(W1[i]));
        g_w2[i] = __uint_as_float(tf32_rna(W2[i]));
    }
}

// ---------------- main fused grouped FFN kernel (launch index 3) ----------------
// 1 CTA = 128 tokens of one expert, 512 threads = 16 warps (8M x 2N) -> 4
// warps/SMSP for latency hiding. Per warp: 16 rows x 128 cols of Y ->
// y[16][4] = 64 regs. Scalar B-fragment loads + k-major tiles (the spill-free
// configuration). Per ff-chunk of 32: GEMM1 (K=256) -> relu+b1 -> H smem ->
// GEMM2 accumulates Y in regs. cp.async double-phase pipeline.

__global__ __launch_bounds__(512)
void pff_main_k(const float* __restrict__ x,
                const float* __restrict__ b1g,
                const float* __restrict__ b2g,
                float* __restrict__ out) {
    extern __shared__ float sm[];
    float* XS  = sm;
    float* B1S = sm + SM_B1;
    float* B2S = sm + SM_B2;
    float* HS  = sm + SM_H;
    int*   TOK = (int*)(sm + SM_TOK);

    // resolve (expert, segment)
    int bid = blockIdx.x;
    int e = -1, seg = 0, cnt = 0, acc = 0;
#pragma unroll
    for (int i = 0; i < NE; i++) {
        int ci = g_cnt[i];
        int nt = (ci + 127) >> 7;
        if (e < 0 && bid < acc + nt) { e = i; seg = bid - acc; cnt = ci; }
        acc += nt;
    }
    if (e < 0) return;

    int tid = threadIdx.x;

    if (tid < 128) {
        int idx = seg * 128 + tid;
        TOK[tid] = (idx < cnt) ? g_list[e * NT + idx] : -1;
    }
    __syncthreads();

    // gather X rows (tf32 RNA), padded rows = 0
    for (int i = tid; i < 128 * 64; i += 512) {
        int r = i >> 6, c4 = i & 63;
        int tk = TOK[r];
        float4 v = make_float4(0.f, 0.f, 0.f, 0.f);
        if (tk >= 0) v = reinterpret_cast<const float4*>(x)[(size_t)tk * 64 + c4];
        uint4 u;
        u.x = tf32_rna(v.x); u.y = tf32_rna(v.y);
        u.z = tf32_rna(v.z); u.w = tf32_rna(v.w);
        *reinterpret_cast<uint4*>(&XS[r * XP + c4 * 4]) = u;
    }

    const float* w1e = g_w1 + (size_t)e * DM * DF;
    const float* w2e = g_w2 + (size_t)e * DF * DM;

    // B1 = W1[0:256, fc*32:+32]  (k-major rows)
    auto issue_b1 = [&](int fc) {
        if (fc < 32) {
#pragma unroll
            for (int t = 0; t < 4; t++) {
                int i = t * 512 + tid;
                int k = i >> 3, c8 = i & 7;
                cp16(&B1S[k * B1P + c8 * 4], w1e + (size_t)k * DF + fc * 32 + c8 * 4);
            }
        }
        CP_COMMIT();
    };
    // B2 = W2[fc*32:+32, 0:256]  (k-major rows)
    auto issue_b2 = [&](int fc) {
        if (fc < 32) {
#pragma unroll
            for (int t = 0; t < 4; t++) {
                int i = t * 512 + tid;
                int k = i >> 6, cc = i & 63;
                cp16(&B2S[k * B2P + cc * 4], w2e + (size_t)(fc * 32 + k) * DM + cc * 4);
            }
        }
        CP_COMMIT();
    };

    int w = tid >> 5, lane = tid & 31;
    int wm = w & 7, wn = w >> 3;        // 8 M-groups x 2 N-groups
    int gidr = lane >> 2, tig = lane & 3;
    int r0w = wm * 16 + gidr;           // this thread's two A rows: r0w, r0w+8

    // Y accumulator: 16 rows x 128 cols per warp -> 64 regs/thread
    float y[16][4];
#pragma unroll
    for (int ns = 0; ns < 16; ns++)
#pragma unroll
        for (int q = 0; q < 4; q++) y[ns][q] = 0.f;

    issue_b1(0);
    issue_b2(0);
    __syncthreads();   // X gather visible before first GEMM1

    for (int fc = 0; fc < 32; fc++) {
        CP_WAIT1();            // B1(fc) landed (B2(fc) may still fly)
        __syncthreads();

        // ---- GEMM1: H32[128x32] = X[128x256] @ W1[:, fc*32:+32] ----
        float h[2][4];
#pragma unroll
        for (int ns = 0; ns < 2; ns++)
#pragma unroll
            for (int q = 0; q < 4; q++) h[ns][q] = 0.f;

#pragma unroll 8
        for (int k0 = 0; k0 < 256; k0 += 8) {
            unsigned a[4];
            {
                uint2 lo = *reinterpret_cast<uint2*>(&XS[r0w * XP + k0 + 2 * tig]);
                uint2 hi = *reinterpret_cast<uint2*>(&XS[(r0w + 8) * XP + k0 + 2 * tig]);
                a[0] = lo.x; a[1] = hi.x; a[2] = lo.y; a[3] = hi.y;
            }
#pragma unroll
            for (int ns = 0; ns < 2; ns++) {
                int n = wn * 16 + ns * 8 + gidr;
                unsigned b0 = __float_as_uint(B1S[(k0 + 2 * tig) * B1P + n]);
                unsigned b1 = __float_as_uint(B1S[(k0 + 2 * tig + 1) * B1P + n]);
                MMA(h[ns], a, b0, b1);
            }
        }
        __syncthreads();       // all warps done reading B1S
        issue_b1(fc + 1);      // prefetch next W1 chunk during H-store + GEMM2

        // ---- relu + b1 -> HS (tf32-rounded: it's the next A operand) ----
#pragma unroll
        for (int ns = 0; ns < 2; ns++) {
            int col = wn * 16 + ns * 8 + 2 * tig;
            float bb0 = __ldg(&b1g[e * DF + fc * 32 + col]);
            float bb1 = __ldg(&b1g[e * DF + fc * 32 + col + 1]);
            uint2 p0, p1;
            p0.x = tf32_rna(fmaxf(h[ns][0] + bb0, 0.f));
            p0.y = tf32_rna(fmaxf(h[ns][1] + bb1, 0.f));
            p1.x = tf32_rna(fmaxf(h[ns][2] + bb0, 0.f));
            p1.y = tf32_rna(fmaxf(h[ns][3] + bb1, 0.f));
            *reinterpret_cast<uint2*>(&HS[r0w * HP + col]) = p0;
            *reinterpret_cast<uint2*>(&HS[(r0w + 8) * HP + col]) = p1;
        }
        CP_WAIT1();            // B2(fc) landed
        __syncthreads();       // + HS visible

        // ---- GEMM2: Y[128x256] += relu(H32) @ W2[fc*32:+32, :] ----
#pragma unroll
        for (int k0 = 0; k0 < 32; k0 += 8) {
            unsigned a[4];
            {
                uint2 lo = *reinterpret_cast<uint2*>(&HS[r0w * HP + k0 + 2 * tig]);
                uint2 hi = *reinterpret_cast<uint2*>(&HS[(r0w + 8) * HP + k0 + 2 * tig]);
                a[0] = lo.x; a[1] = hi.x; a[2] = lo.y; a[3] = hi.y;
            }
#pragma unroll
            for (int ns = 0; ns < 16; ns++) {
                int n = wn * 128 + ns * 8 + gidr;
                unsigned b0 = __float_as_uint(B2S[(k0 + 2 * tig) * B2P + n]);
                unsigned b1 = __float_as_uint(B2S[(k0 + 2 * tig + 1) * B2P + n]);
                MMA(y[ns], a, b0, b1);
            }
        }
        __syncthreads();       // all warps done reading B2S (and HS)
        issue_b2(fc + 1);      // prefetch next W2 chunk during next GEMM1
    }

    // ---- epilogue: Y + b2 -> scatter to out[token] ----
    {
        int tk0 = TOK[r0w], tk1 = TOK[r0w + 8];
#pragma unroll
        for (int ns = 0; ns < 16; ns++) {
            int col = wn * 128 + ns * 8 + 2 * tig;
            float bb0 = __ldg(&b2g[e * DM + col]);
            float bb1 = __ldg(&b2g[e * DM + col + 1]);
            if (tk0 >= 0) {
                float2 v;
                v.x = y[ns][0] + bb0;
                v.y = y[ns][1] + bb1;
                *reinterpret_cast<float2*>(&out[(size_t)tk0 * DM + col]) = v;
            }
            if (tk1 >= 0) {
                float2 v;
                v.x = y[ns][2] + bb0;
                v.y = y[ns][3] + bb1;
                *reinterpret_cast<float2*>(&out[(size_t)tk1 * DM + col]) = v;
            }
        }
    }
}

// ---------------- launch ----------------

extern "C" void kernel_launch(void* const* d_in, const int* in_sizes, int n_in,
                              void* d_out, int out_size) {
    const float* x     = (const float*)d_in[0];
    const float* W1    = (const float*)d_in[1];
    const float* b1    = (const float*)d_in[2];
    const float* W2    = (const float*)d_in[3];
    const float* b2    = (const float*)d_in[4];
    const int*   b_seq = (const int*)d_in[5];
    float* out = (float*)d_out;

    cudaFuncSetAttribute(pff_main_k, cudaFuncAttributeMaxDynamicSharedMemorySize,
                         SM_BYTES);

    // 4 launches; pff_main_k at index 3 (confirmed ncu target)
    zero_inactive_cnt_k<<<NT / 8, 256>>>(b_seq, (float4*)out);
    build_lists_k<<<NT / 256, 256>>>(b_seq);
    prep_w_k<<<(NE * DM * DF + 255) / 256, 256>>>(W1, W2);
    pff_main_k<<<516, 512, SM_BYTES>>>(x, b1, b2, out);
}

// round 10
// speedup vs baseline: 1.1155x; 1.1155x over previous
#include <cuda_runtime.h>
#include <cstdint>

#define DM 256
#define DF 1024
#define NE 4
#define NT 65536

// smem pitches (floats) — all hot-loop LDS conflict-free (proven R6):
//  A-frag uint2 loads need pitch % 32 == 8  -> XP=264, HP=40
//  B-frag scalar loads need 2*pitch % 32 == 8 -> B1P=36, B2P=260
#define XP   264   // X tile  [128 r][256 k]
#define B1P  36    // B1 tile [256 k][32 n]
#define B2P  260   // B2 tile [32 k][256 n]
#define HP   40    // H tile  [128 r][32 k]

#define SM_B1    (128 * XP)             // 33792
#define SM_B2    (SM_B1 + 256 * B1P)    // 43008
#define SM_H     (SM_B2 + 32 * B2P)     // 51328
#define SM_BIAS1 (SM_H + 128 * HP)      // 56448
#define SM_BIAS2 (SM_BIAS1 + DF)        // 57472
#define SM_TOK   (SM_BIAS2 + DM)        // 57728
#define SM_FLOATS (SM_TOK + 128)        // 57856
#define SM_BYTES  (SM_FLOATS * 4)       // 231424 bytes (<= 232448 cap)

__device__ int   g_cnt[NE];
__device__ int   g_list[NE * NT];
__device__ float g_w1[NE * DM * DF];   // native layout, tf32-rounded
__device__ float g_w2[NE * DF * DM];   // native layout, tf32-rounded

__device__ __forceinline__ unsigned tf32_rna(float f) {
    unsigned u;
    asm("cvt.rna.tf32.f32 %0, %1;" : "=r"(u) : "f"(f));
    return u;
}

__device__ __forceinline__ void cp16(void* s, const void* g) {
    uint32_t sa = (uint32_t)__cvta_generic_to_shared(s);
    asm volatile("cp.async.cg.shared.global [%0], [%1], 16;" :: "r"(sa), "l"(g));
}

#define CP_COMMIT() asm volatile("cp.async.commit_group;")
#define CP_WAIT1()  asm volatile("cp.async.wait_group 1;")

// D += A*B for m16n8k8 tf32 (fp32 accumulate)
#define MMA(d, a, b0, b1)                                                    \
    asm volatile(                                                            \
        "mma.sync.aligned.m16n8k8.row.col.f32.tf32.tf32.f32 "                \
        "{%0,%1,%2,%3},{%4,%5,%6,%7},{%8,%9},{%0,%1,%2,%3};"                 \
        : "+f"((d)[0]), "+f"((d)[1]), "+f"((d)[2]), "+f"((d)[3])             \
        : "r"((a)[0]), "r"((a)[1]), "r"((a)[2]), "r"((a)[3]),                \
          "r"(b0), "r"(b1))

// ---------------- prep kernels ----------------

// launch 0: zero inactive output rows (warp-per-token) + zero counters
__global__ void zero_inactive_cnt_k(const int* __restrict__ b_seq,
                                    float4* __restrict__ out4) {
    if (blockIdx.x == 0 && threadIdx.x < NE) g_cnt[threadIdx.x] = 0;
    int w = (blockIdx.x * blockDim.x + threadIdx.x) >> 5;
    int lane = threadIdx.x & 31;
    if (b_seq[w] == 0) {
        float4 z = make_float4(0.f, 0.f, 0.f, 0.f);
        out4[(size_t)w * 64 + lane] = z;
        out4[(size_t)w * 64 + 32 + lane] = z;
    }
}

// launch 1
__global__ void build_lists_k(const int* __restrict__ b_seq) {
    int t = blockIdx.x * blockDim.x + threadIdx.x;
    if (t < NT) {
        int b = b_seq[t];
        if (b > 0) {
            int p = atomicAdd(&g_cnt[b - 1], 1);
            g_list[(b - 1) * NT + p] = t;
        }
    }
}

// launch 2: tf32-round both weight tensors
__global__ void prep_w_k(const float* __restrict__ W1,
                         const float* __restrict__ W2) {
    int i = blockIdx.x * blockDim.x + threadIdx.x;
    if (i < NE * DM * DF) {
        g_w1[i] = __uint_as_float(tf32_rna(W1[i]));
        g_w2[i] = __uint_as_float(tf32_rna(W2[i]));
    }
}

// ---------------- main fused grouped FFN kernel (launch 3) ----------------
// 1 CTA = 128 tokens of one expert, 256 threads = 8 warps.
// GEMM1 warp grid 4M x 2N (square (2,2) per k-iter — optimal).
// GEMM2 warp grid 2M x 4N (ms=4, ns=8): loads/MMA 0.75 vs 1.125 before.
// Biases cached in smem. Per ff-chunk of 32: GEMM1 (K=256) -> relu+b1 ->
// H smem -> GEMM2 accumulates Y[128x256] in regs. cp.async pipeline.

__global__ __launch_bounds__(256, 1)
void pff_main_k(const float* __restrict__ x,
                const float* __restrict__ b1g,
                const float* __restrict__ b2g,
                float* __restrict__ out) {
    extern __shared__ float sm[];
    float* XS  = sm;
    float* B1S = sm + SM_B1;
    float* B2S = sm + SM_B2;
    float* HS  = sm + SM_H;
    float* BS1 = sm + SM_BIAS1;
    float* BS2 = sm + SM_BIAS2;
    int*   TOK = (int*)(sm + SM_TOK);

    // resolve (expert, segment)
    int bid = blockIdx.x;
    int e = -1, seg = 0, cnt = 0, acc = 0;
#pragma unroll
    for (int i = 0; i < NE; i++) {
        int ci = g_cnt[i];
        int nt = (ci + 127) >> 7;
        if (e < 0 && bid < acc + nt) { e = i; seg = bid - acc; cnt = ci; }
        acc += nt;
    }
    if (e < 0) return;

    int tid = threadIdx.x;

    if (tid < 128) {
        int idx = seg * 128 + tid;
        TOK[tid] = (idx < cnt) ? g_list[e * NT + idx] : -1;
    }
    // biases into smem
#pragma unroll
    for (int t = 0; t < 4; t++) BS1[t * 256 + tid] = b1g[e * DF + t * 256 + tid];
    BS2[tid] = b2g[e * DM + tid];
    __syncthreads();

    // gather X rows (tf32 RNA), padded rows = 0
    for (int i = tid; i < 128 * 64; i += 256) {
        int r = i >> 6, c4 = i & 63;
        int tk = TOK[r];
        float4 v = make_float4(0.f, 0.f, 0.f, 0.f);
        if (tk >= 0) v = reinterpret_cast<const float4*>(x)[(size_t)tk * 64 + c4];
        uint4 u;
        u.x = tf32_rna(v.x); u.y = tf32_rna(v.y);
        u.z = tf32_rna(v.z); u.w = tf32_rna(v.w);
        *reinterpret_cast<uint4*>(&XS[r * XP + c4 * 4]) = u;
    }

    const float* w1e = g_w1 + (size_t)e * DM * DF;
    const float* w2e = g_w2 + (size_t)e * DF * DM;

    // B1 = W1[0:256, fc*32:+32]  (k-major rows)
    auto issue_b1 = [&](int fc) {
        if (fc < 32) {
            for (int i = tid; i < 2048; i += 256) {
                int k = i >> 3, c8 = i & 7;
                cp16(&B1S[k * B1P + c8 * 4], w1e + (size_t)k * DF + fc * 32 + c8 * 4);
            }
        }
        CP_COMMIT();
    };
    // B2 = W2[fc*32:+32, 0:256]  (k-major rows)
    auto issue_b2 = [&](int fc) {
        if (fc < 32) {
            for (int i = tid; i < 2048; i += 256) {
                int k = i >> 6, cc = i & 63;
                cp16(&B2S[k * B2P + cc * 4], w2e + (size_t)(fc * 32 + k) * DM + cc * 4);
            }
        }
        CP_COMMIT();
    };

    int w = tid >> 5, lane = tid & 31;
    int wm = w & 3, wn = w >> 2;        // GEMM1: 4M x 2N
    int wm2 = w & 1, wn4 = w >> 1;      // GEMM2: 2M x 4N
    int gidr = lane >> 2, tig = lane & 3;

    // Y accumulator: per warp 64 rows x 64 cols -> y[4][8][4] = 128 regs
    float y[4][8][4];
#pragma unroll
    for (int ms = 0; ms < 4; ms++)
#pragma unroll
        for (int ns = 0; ns < 8; ns++)
#pragma unroll
            for (int q = 0; q < 4; q++) y[ms][ns][q] = 0.f;

    issue_b1(0);
    issue_b2(0);
    __syncthreads();   // X gather + biases visible

    for (int fc = 0; fc < 32; fc++) {
        CP_WAIT1();            // B1(fc) landed (B2(fc) may still fly)
        __syncthreads();

        // ---- GEMM1: H32[128x32] = X[128x256] @ W1[:, fc*32:+32] ----
        float h[2][2][4];
#pragma unroll
        for (int ms = 0; ms < 2; ms++)
#pragma unroll
            for (int ns = 0; ns < 2; ns++)
#pragma unroll
                for (int q = 0; q < 4; q++) h[ms][ns][q] = 0.f;

#pragma unroll
        for (int k0 = 0; k0 < 256; k0 += 8) {
            unsigned a[2][4];
#pragma unroll
            for (int ms = 0; ms < 2; ms++) {
                int r = wm * 32 + ms * 16 + gidr;
                uint2 lo = *reinterpret_cast<uint2*>(&XS[r * XP + k0 + 2 * tig]);
                uint2 hi = *reinterpret_cast<uint2*>(&XS[(r + 8) * XP + k0 + 2 * tig]);
                a[ms][0] = lo.x; a[ms][1] = hi.x; a[ms][2] = lo.y; a[ms][3] = hi.y;
            }
#pragma unroll
            for (int ns = 0; ns < 2; ns++) {
                int n = wn * 16 + ns * 8 + gidr;
                unsigned b0 = __float_as_uint(B1S[(k0 + 2 * tig) * B1P + n]);
                unsigned b1 = __float_as_uint(B1S[(k0 + 2 * tig + 1) * B1P + n]);
                MMA(h[0][ns], a[0], b0, b1);
                MMA(h[1][ns], a[1], b0, b1);
            }
        }
        __syncthreads();       // all warps done reading B1S
        issue_b1(fc + 1);      // prefetch next W1 chunk during H-store + GEMM2

        // ---- relu + b1 -> HS (tf32-rounded: it's the next A operand) ----
#pragma unroll
        for (int ms = 0; ms < 2; ms++) {
            int r = wm * 32 + ms * 16 + gidr;
#pragma unroll
            for (int ns = 0; ns < 2; ns++) {
                int col = wn * 16 + ns * 8 + 2 * tig;
                float bb0 = BS1[fc * 32 + col];
                float bb1 = BS1[fc * 32 + col + 1];
                uint2 p0, p1;
                p0.x = tf32_rna(fmaxf(h[ms][ns][0] + bb0, 0.f));
                p0.y = tf32_rna(fmaxf(h[ms][ns][1] + bb1, 0.f));
                p1.x = tf32_rna(fmaxf(h[ms][ns][2] + bb0, 0.f));
                p1.y = tf32_rna(fmaxf(h[ms][ns][3] + bb1, 0.f));
                *reinterpret_cast<uint2*>(&HS[r * HP + col]) = p0;
                *reinterpret_cast<uint2*>(&HS[(r + 8) * HP + col]) = p1;
            }
        }
        CP_WAIT1();            // B2(fc) landed
        __syncthreads();       // + HS visible

        // ---- GEMM2 (2M x 4N): Y += relu(H32) @ W2[fc*32:+32, :] ----
#pragma unroll
        for (int k0 = 0; k0 < 32; k0 += 8) {
            unsigned a[4][4];
#pragma unroll
            for (int ms = 0; ms < 4; ms++) {
                int r = wm2 * 64 + ms * 16 + gidr;
                uint2 lo = *reinterpret_cast<uint2*>(&HS[r * HP + k0 + 2 * tig]);
                uint2 hi = *reinterpret_cast<uint2*>(&HS[(r + 8) * HP + k0 + 2 * tig]);
                a[ms][0] = lo.x; a[ms][1] = hi.x; a[ms][2] = lo.y; a[ms][3] = hi.y;
            }
#pragma unroll
            for (int ns = 0; ns < 8; ns++) {
                int n = wn4 * 64 + ns * 8 + gidr;
                unsigned b0 = __float_as_uint(B2S[(k0 + 2 * tig) * B2P + n]);
                unsigned b1 = __float_as_uint(B2S[(k0 + 2 * tig + 1) * B2P + n]);
#pragma unroll
                for (int ms = 0; ms < 4; ms++)
                    MMA(y[ms][ns], a[ms], b0, b1);
            }
        }
        __syncthreads();       // all warps done reading B2S (and HS)
        issue_b2(fc + 1);      // prefetch next W2 chunk during next GEMM1
    }

    // ---- epilogue: Y + b2 -> scatter to out[token] (GEMM2 tiling) ----
#pragma unroll
    for (int ms = 0; ms < 4; ms++) {
        int r = wm2 * 64 + ms * 16 + gidr;
        int tk0 = TOK[r], tk1 = TOK[r + 8];
#pragma unroll
        for (int ns = 0; ns < 8; ns++) {
            int col = wn4 * 64 + ns * 8 + 2 * tig;
            float bb0 = BS2[col];
            float bb1 = BS2[col + 1];
            if (tk0 >= 0) {
                float2 v;
                v.x = y[ms][ns][0] + bb0;
                v.y = y[ms][ns][1] + bb1;
                *reinterpret_cast<float2*>(&out[(size_t)tk0 * DM + col]) = v;
            }
            if (tk1 >= 0) {
                float2 v;
                v.x = y[ms][ns][2] + bb0;
                v.y = y[ms][ns][3] + bb1;
                *reinterpret_cast<float2*>(&out[(size_t)tk1 * DM + col]) = v;
            }
        }
    }
}

// ---------------- launch ----------------

extern "C" void kernel_launch(void* const* d_in, const int* in_sizes, int n_in,
                              void* d_out, int out_size) {
    const float* x     = (const float*)d_in[0];
    const float* W1    = (const float*)d_in[1];
    const float* b1    = (const float*)d_in[2];
    const float* W2    = (const float*)d_in[3];
    const float* b2    = (const float*)d_in[4];
    const int*   b_seq = (const int*)d_in[5];
    float* out = (float*)d_out;

    cudaFuncSetAttribute(pff_main_k, cudaFuncAttributeMaxDynamicSharedMemorySize,
                         SM_BYTES);

    // 4 launches; pff_main_k at index 3 (confirmed ncu target)
    zero_inactive_cnt_k<<<NT / 8, 256>>>(b_seq, (float4*)out);
    build_lists_k<<<NT / 256, 256>>>(b_seq);
    prep_w_k<<<(NE * DM * DF + 255) / 256, 256>>>(W1, W2);
    pff_main_k<<<516, 256, SM_BYTES>>>(x, b1, b2, out);
}